// round 8
// baseline (speedup 1.0000x reference)
#include <cuda_runtime.h>
#include <cstdint>

// MMI softmax loss — collapsed gather form, single launch, one-stage reduce.
//
//   out = -(1/2048) * sum_d  emb[d, t_d] / (sum_{j=1..4} emb[d + j*2048, t_d])
//
// 64 single-warp blocks gather 5 scalars per d and warp-reduce. Each block
// leader adds its partial into ONE global Q32.32 fixed-point accumulator via
// fire-and-forget red.add.u64 (integer adds commute -> bit-deterministic
// regardless of arrival order), then arrives on an acq_rel counter. The last
// arriver acquires, reads the accumulator once, converts, writes the scalar,
// and re-arms both words for graph replay. No fences, no second shuffle tree.

#define DIM   2048
#define NCLS  32000LL
#define NBLK  64
#define TPB   32    // NBLK * TPB == DIM, one d per thread, one warp per block

__device__ unsigned long long g_acc   = 0ULL;  // Q32.32 accumulator
__device__ unsigned int       g_count = 0;     // arrival counter (left at 0)

__global__ void mmi_fused_kernel(const float* __restrict__ emb,
                                 const int* __restrict__ tgt,
                                 float* __restrict__ out) {
    const int lane = threadIdx.x;
    const int d = blockIdx.x * TPB + lane;          // 0..2047, exact cover

    const int t = __ldg(&tgt[d]);                   // coalesced: 1 line/warp
    const float* col = emb + (long long)t;

    // 5 independent gathers (MLP=5 per thread; latency overlapped)
    const float ex = __ldg(col + (long long)d * NCLS);
    const float c0 = __ldg(col + (long long)(d + 1 * DIM) * NCLS);
    const float c1 = __ldg(col + (long long)(d + 2 * DIM) * NCLS);
    const float c2 = __ldg(col + (long long)(d + 3 * DIM) * NCLS);
    const float c3 = __ldg(col + (long long)(d + 4 * DIM) * NCLS);

    // fast divide: MUFU.RCP + mul (2^-22 rel err, far under 1e-3 budget)
    float v = __fdividef(ex, ((c0 + c1) + c2) + c3);

    // intra-warp reduce (fixed tree)
    #pragma unroll
    for (int o = 16; o; o >>= 1)
        v += __shfl_xor_sync(0xffffffffu, v, o);

    if (lane == 0) {
        // Q32.32 encode in double (exact for these magnitudes' useful bits)
        unsigned long long enc =
            (unsigned long long)((double)v * 4294967296.0);

        unsigned prev;
        // red: fire-and-forget, relaxed; the acq_rel on the counter releases
        // it (same-thread prior op) and pairs with the last arriver's acquire.
        asm volatile(
            "red.relaxed.gpu.global.add.u64 [%1], %2;\n\t"
            "atom.acq_rel.gpu.global.add.u32 %0, [%3], 1;\n\t"
            : "=r"(prev)
            : "l"(&g_acc), "l"(enc), "l"(&g_count)
            : "memory");

        if (prev == (unsigned)(NBLK - 1)) {
            unsigned long long total;
            asm volatile("ld.acquire.gpu.global.u64 %0, [%1];"
                         : "=l"(total) : "l"(&g_acc) : "memory");
            double s = (double)total * (1.0 / 4294967296.0);
            *out = (float)(-(s / (double)DIM));
            // re-arm for next graph replay (visible at kernel boundary)
            g_acc   = 0ULL;
            g_count = 0u;
        }
    }
}

extern "C" void kernel_launch(void* const* d_in, const int* in_sizes, int n_in,
                              void* d_out, int out_size) {
    const float* emb = (const float*)d_in[0];   // embeddings [10240, 32000] f32
    const int*   tgt = (const int*)d_in[1];     // targets [2048] i32

    mmi_fused_kernel<<<NBLK, TPB>>>(emb, tgt, (float*)d_out);
}